// round 16
// baseline (speedup 1.0000x reference)
#include <cuda_runtime.h>
#include <cuda_fp16.h>
#include <cstdint>

// Problem constants (fixed by the reference setup_inputs)
#define OUT_F 2048
#define IN_F  2048
#define NNZ_PER_ROW 128
#define NTOK 512

#define NTOK8 (NTOK / 8)   // 64 uint4 (8-half) chunks per xTh row
#define NCTAS 2048         // one CTA per output row; ALL co-resident (14/SM x 148 = 2072)

// Scratch
__device__ __align__(16) __half g_xTh[IN_F * NTOK];  // 2 MB  xT fp16
__device__ __align__(16) float  g_yT[OUT_F * NTOK];  // 4 MB  yT staging fp32

// Grid barrier state (count self-resets every barrier -> graph-replay safe;
// gen grows monotonically across replays, never reset)
__device__ volatile int g_bar_gen;
__device__ int g_bar_count;

__device__ __forceinline__ void grid_barrier() {
    __syncthreads();
    if (threadIdx.x == 0) {
        __threadfence();                       // release: my stores visible
        const int gen = g_bar_gen;
        if (atomicAdd(&g_bar_count, 1) == NCTAS - 1) {
            g_bar_count = 0;                   // reset BEFORE releasing
            __threadfence();
            g_bar_gen = gen + 1;               // release all
        } else {
            while (g_bar_gen == gen) __nanosleep(32);
        }
        __threadfence();                       // acquire: others' stores visible
    }
    __syncthreads();
}

// ---------------------------------------------------------------------------
// One persistent kernel: transpose-x | barrier | spmm | barrier | transpose-y.
// 2048 CTAs x 128 threads, __launch_bounds__(128, 14): 2072 resident slots
// >= 2048 -> every CTA co-resident, so the software barrier cannot deadlock.
// ---------------------------------------------------------------------------
__global__ __launch_bounds__(128, 14) void fused_kernel(
    const float* __restrict__ x,
    const float* __restrict__ data,
    const int*   __restrict__ indices,
    float*       __restrict__ out)
{
    __shared__ float s_t[16][33];        // transpose tile (phases 1 & 3)
    __shared__ int2  s_iw[NNZ_PER_ROW];  // CSR entries (phase 2)
    __shared__ float s_red[NTOK];        // k-split partials (phase 2)

    const int bid = blockIdx.x;
    const int tid = threadIdx.x;

    // ======== Phase 1: x[512,2048] f32 -> g_xTh[2048,512] f16 ========
    // 2048 tiles of 16 tokens x 32 features (2x the CTA parallelism of the
    // old standalone transpose). Loads coalesced 128B; stores 8B half2 pairs,
    // 32B-aligned full sectors per feature row.
    {
        const int f0   = (bid & 63) * 32;    // feature tile origin
        const int tok0 = (bid >> 6) * 16;    // token tile origin
        const int lane = tid & 31;
#pragma unroll
        for (int i = 0; i < 4; i++) {
            const int tok = i * 4 + (tid >> 5);
            s_t[tok][lane] = x[(size_t)(tok0 + tok) * IN_F + f0 + lane];
        }
        __syncthreads();

        const int feat = tid >> 2;           // [0,32)
        const int hp   = tid & 3;            // 4-token group [0,4)
        const __half2 h0 = __floats2half2_rn(s_t[hp * 4 + 0][feat], s_t[hp * 4 + 1][feat]);
        const __half2 h1 = __floats2half2_rn(s_t[hp * 4 + 2][feat], s_t[hp * 4 + 3][feat]);
        __half2* dst = reinterpret_cast<__half2*>(
            g_xTh + (size_t)(f0 + feat) * NTOK + tok0 + hp * 4);
        dst[0] = h0;
        dst[1] = h1;
    }

    grid_barrier();

    // ======== Phase 2: gather-SpMM (proven R9 structure, verbatim) ========
    // Row r = bid. 128 threads: k-split 2 (threads [0,64) do k 0..63,
    // [64,128) do k 64..127), each thread owns 8 tokens via one uint4 gather
    // per k. Coalesced float4 stores into yT.
    {
        const int e = bid * NNZ_PER_ROW + tid;
        s_iw[tid] = make_int2(indices[e] * NTOK8, __float_as_int(data[e]));
        __syncthreads();

        const int half = tid >> 6;
        const int lt   = tid & 63;

        const uint4* __restrict__ xT4h = reinterpret_cast<const uint4*>(g_xTh);

        float acc[8];
#pragma unroll
        for (int j = 0; j < 8; j++) acc[j] = 0.f;

        const int kbase = half * 64;

#pragma unroll 8
        for (int k = 0; k < 64; ++k) {
            const int2 iw = s_iw[kbase + k];
            const float w = __int_as_float(iw.y);
            const uint4 v = __ldg(&xT4h[iw.x + lt]);

            const float2 f0 = __half22float2(*reinterpret_cast<const __half2*>(&v.x));
            const float2 f1 = __half22float2(*reinterpret_cast<const __half2*>(&v.y));
            const float2 f2 = __half22float2(*reinterpret_cast<const __half2*>(&v.z));
            const float2 f3 = __half22float2(*reinterpret_cast<const __half2*>(&v.w));

            acc[0] = fmaf(w, f0.x, acc[0]);
            acc[1] = fmaf(w, f0.y, acc[1]);
            acc[2] = fmaf(w, f1.x, acc[2]);
            acc[3] = fmaf(w, f1.y, acc[3]);
            acc[4] = fmaf(w, f2.x, acc[4]);
            acc[5] = fmaf(w, f2.y, acc[5]);
            acc[6] = fmaf(w, f3.x, acc[6]);
            acc[7] = fmaf(w, f3.y, acc[7]);
        }

        // k-reduce: half 1 publishes, half 0 combines + stores coalesced.
        if (half == 1) {
#pragma unroll
            for (int j = 0; j < 8; j++) s_red[lt * 8 + j] = acc[j];
        }
        __syncthreads();

        if (half == 0) {
#pragma unroll
            for (int j = 0; j < 8; j++) acc[j] += s_red[lt * 8 + j];

            float4* __restrict__ dst =
                reinterpret_cast<float4*>(g_yT + (size_t)bid * NTOK + 8 * lt);
            dst[0] = make_float4(acc[0], acc[1], acc[2], acc[3]);
            dst[1] = make_float4(acc[4], acc[5], acc[6], acc[7]);
        }
    }

    grid_barrier();

    // ======== Phase 3: g_yT[2048,512] f32 -> out[512,2048] ========
    // 2048 tiles of 16 features x 32 tokens. Loads coalesced 128B; stores
    // float4 (64B-aligned, full sectors) along the feature dim.
    {
        const int f0   = (bid & 127) * 16;   // feature tile origin
        const int tok0 = (bid >> 7) * 32;    // token tile origin
        const int lane = tid & 31;
#pragma unroll
        for (int i = 0; i < 4; i++) {
            const int feat = i * 4 + (tid >> 5);
            s_t[feat][lane] = g_yT[(size_t)(f0 + feat) * NTOK + tok0 + lane];
        }
        __syncthreads();

        const int tok = tid >> 2;            // [0,32)
        const int q   = tid & 3;             // feature-float4 [0,4)
        const float4 o = make_float4(s_t[4 * q + 0][tok], s_t[4 * q + 1][tok],
                                     s_t[4 * q + 2][tok], s_t[4 * q + 3][tok]);
        *reinterpret_cast<float4*>(out + (size_t)(tok0 + tok) * OUT_F + f0 + 4 * q) = o;
    }
}

// ---------------------------------------------------------------------------
// Launcher
// Inputs (metadata order): 0=x f32[512*2048], 1=data f32[262144],
//                          2=indices i32[262144], 3=indptr i32[2049] (uniform, unused)
// Output: f32[512*2048]
// ---------------------------------------------------------------------------
extern "C" void kernel_launch(void* const* d_in, const int* in_sizes, int n_in,
                              void* d_out, int out_size) {
    const float* x       = (const float*)d_in[0];
    const float* data    = (const float*)d_in[1];
    const int*   indices = (const int*)d_in[2];
    float*       out     = (float*)d_out;

    fused_kernel<<<NCTAS, 128>>>(x, data, indices, out);
}

// round 17
// speedup vs baseline: 1.3305x; 1.3305x over previous
#include <cuda_runtime.h>
#include <cuda_fp16.h>
#include <cuda_bf16.h>
#include <cstdint>

// Problem constants (fixed by the reference setup_inputs)
#define OUT_F 2048
#define IN_F  2048
#define NNZ_PER_ROW 128
#define NTOK 512

#define NTOK8 (NTOK / 8)   // 64 uint4 (8-half) chunks per xTh row

// Scratch: transposed activations in FP16 (2 MB), output staging in FP32 (4 MB).
__device__ __align__(16) __half g_xTh[IN_F * NTOK];  // 2 MB
__device__ __align__(16) float  g_yT[OUT_F * NTOK];  // 4 MB

// ---------------------------------------------------------------------------
// Kernel 1: transpose + downconvert x[NTOK, IN_F] f32 -> g_xTh[IN_F, NTOK] f16
// R8/R9-proven body. Triggers the dependent spmm launch after its stores.
// ---------------------------------------------------------------------------
__global__ __launch_bounds__(256) void transpose_x_kernel(const float* __restrict__ x) {
    __shared__ float tile[32][33];

    int col = blockIdx.x * 32 + threadIdx.x;   // IN_F dim
    int row = blockIdx.y * 32 + threadIdx.y;   // NTOK dim

#pragma unroll
    for (int j = 0; j < 32; j += 8) {
        tile[threadIdx.y + j][threadIdx.x] = x[(row + j) * IN_F + col];
    }
    __syncthreads();

    int ocol = blockIdx.y * 32 + threadIdx.x;  // NTOK dim (contiguous out)
    int orow = blockIdx.x * 32 + threadIdx.y;  // IN_F dim

#pragma unroll
    for (int j = 0; j < 32; j += 8) {
        g_xTh[(orow + j) * NTOK + ocol] = __float2half_rn(tile[threadIdx.x][threadIdx.y + j]);
    }

    cudaTriggerProgrammaticLaunchCompletion();
}

// ---------------------------------------------------------------------------
// Kernel 2: gather-SpMM (R9-proven body, verbatim mainloop).
// PDL: stages CSR entries (independent of xTh) BEFORE the grid-dependency
// sync, overlapping with transpose_x's tail; then gathers.
// One CTA per output row; 128 threads, k-split 2, uint4 8-half gathers.
// Grid = 2048 CTAs, single resident wave (14 x 148 = 2072 slots).
// ---------------------------------------------------------------------------
__global__ __launch_bounds__(128, 14) void spmm_kernel(
    const float* __restrict__ data,
    const int*   __restrict__ indices)
{
    __shared__ int2  s_iw[NNZ_PER_ROW];      // 1 KB
    __shared__ float s_red[64 * 8];          // 2 KB partial sums

    const int r0  = blockIdx.x;
    const int tid = threadIdx.x;

    // ---- PDL prologue: independent of xTh, runs under transpose_x ----
    {
        const int e = r0 * NNZ_PER_ROW + tid;
        s_iw[tid] = make_int2(indices[e] * NTOK8, __float_as_int(data[e]));
    }
    __syncthreads();

    // Wait for transpose_x's writes to be visible.
    cudaGridDependencySynchronize();

    const int half = tid >> 6;    // k-partition: 0 or 1
    const int lt   = tid & 63;    // token-chunk lane: 8 tokens each

    const uint4* __restrict__ xT4h = reinterpret_cast<const uint4*>(g_xTh);

    float acc[8];
#pragma unroll
    for (int j = 0; j < 8; j++) acc[j] = 0.f;

    const int kbase = half * 64;

#pragma unroll 8
    for (int k = 0; k < 64; ++k) {
        const int2 iw = s_iw[kbase + k];
        const float w = __int_as_float(iw.y);
        const uint4 v = __ldg(&xT4h[iw.x + lt]);

        const float2 f0 = __half22float2(*reinterpret_cast<const __half2*>(&v.x));
        const float2 f1 = __half22float2(*reinterpret_cast<const __half2*>(&v.y));
        const float2 f2 = __half22float2(*reinterpret_cast<const __half2*>(&v.z));
        const float2 f3 = __half22float2(*reinterpret_cast<const __half2*>(&v.w));

        acc[0] = fmaf(w, f0.x, acc[0]);
        acc[1] = fmaf(w, f0.y, acc[1]);
        acc[2] = fmaf(w, f1.x, acc[2]);
        acc[3] = fmaf(w, f1.y, acc[3]);
        acc[4] = fmaf(w, f2.x, acc[4]);
        acc[5] = fmaf(w, f2.y, acc[5]);
        acc[6] = fmaf(w, f3.x, acc[6]);
        acc[7] = fmaf(w, f3.y, acc[7]);
    }

    // Reduce the two k-partitions: half 1 publishes, half 0 combines + stores.
    if (half == 1) {
#pragma unroll
        for (int j = 0; j < 8; j++) s_red[lt * 8 + j] = acc[j];
    }
    __syncthreads();

    if (half == 0) {
#pragma unroll
        for (int j = 0; j < 8; j++) acc[j] += s_red[lt * 8 + j];

        float4* __restrict__ dst =
            reinterpret_cast<float4*>(g_yT + (size_t)r0 * NTOK + 8 * lt);
        dst[0] = make_float4(acc[0], acc[1], acc[2], acc[3]);
        dst[1] = make_float4(acc[4], acc[5], acc[6], acc[7]);
    }

    cudaTriggerProgrammaticLaunchCompletion();
}

// ---------------------------------------------------------------------------
// Kernel 3: transpose g_yT[OUT_F, NTOK] -> out[NTOK, OUT_F]  (R9-proven body).
// PDL: launch ramp overlaps spmm's tail; sync before touching yT.
// ---------------------------------------------------------------------------
__global__ __launch_bounds__(256) void transpose_y_kernel(float* __restrict__ out) {
    __shared__ float tile[32][33];

    cudaGridDependencySynchronize();

    int col = blockIdx.x * 32 + threadIdx.x;   // NTOK dim (contiguous in yT)
    int row = blockIdx.y * 32 + threadIdx.y;   // OUT_F dim

#pragma unroll
    for (int j = 0; j < 32; j += 8) {
        tile[threadIdx.y + j][threadIdx.x] = g_yT[(row + j) * NTOK + col];
    }
    __syncthreads();

    int ocol = blockIdx.y * 32 + threadIdx.x;  // OUT_F dim (contiguous in out)
    int orow = blockIdx.x * 32 + threadIdx.y;  // NTOK dim

#pragma unroll
    for (int j = 0; j < 32; j += 8) {
        out[(orow + j) * OUT_F + ocol] = tile[threadIdx.x][threadIdx.y + j];
    }
}

// ---------------------------------------------------------------------------
// Launcher — PDL chain: tx ==PDL==> spmm ==PDL==> ty
// Inputs (metadata order): 0=x f32[512*2048], 1=data f32[262144],
//                          2=indices i32[262144], 3=indptr i32[2049] (uniform, unused)
// Output: f32[512*2048]
// ---------------------------------------------------------------------------
extern "C" void kernel_launch(void* const* d_in, const int* in_sizes, int n_in,
                              void* d_out, int out_size) {
    const float* x       = (const float*)d_in[0];
    const float* data    = (const float*)d_in[1];
    const int*   indices = (const int*)d_in[2];
    float*       out     = (float*)d_out;

    // Kernel 1: plain launch
    dim3 tblk(32, 8);
    dim3 xgrid(IN_F / 32, NTOK / 32);   // (64, 16) = 1024 CTAs
    transpose_x_kernel<<<xgrid, tblk>>>(x);

    // Kernel 2: PDL-dependent on kernel 1
    {
        cudaLaunchAttribute attr[1];
        attr[0].id = cudaLaunchAttributeProgrammaticStreamSerialization;
        attr[0].val.programmaticStreamSerializationAllowed = 1;
        cudaLaunchConfig_t cfg = {};
        cfg.gridDim  = dim3(OUT_F, 1, 1);   // 2048 CTAs
        cfg.blockDim = dim3(128, 1, 1);
        cfg.attrs    = attr;
        cfg.numAttrs = 1;
        cudaLaunchKernelEx(&cfg, spmm_kernel, data, indices);
    }

    // Kernel 3: PDL-dependent on kernel 2
    {
        cudaLaunchAttribute attr[1];
        attr[0].id = cudaLaunchAttributeProgrammaticStreamSerialization;
        attr[0].val.programmaticStreamSerializationAllowed = 1;
        cudaLaunchConfig_t cfg = {};
        cfg.gridDim  = dim3(NTOK / 32, OUT_F / 32, 1);   // (16, 64)
        cfg.blockDim = dim3(32, 8, 1);
        cfg.attrs    = attr;
        cfg.numAttrs = 1;
        cudaLaunchKernelEx(&cfg, transpose_y_kernel, out);
    }
}